// round 1
// baseline (speedup 1.0000x reference)
#include <cuda_runtime.h>
#include <math.h>

#define BATCH      2000000
#define EMB_DIM    32
#define LAM        0.1

// Global accumulators: [0]=bce, [1]=sum(u*u), [2]=sum(v*v)
__device__ double g_acc[3];

__global__ void zero_acc_kernel() {
    if (threadIdx.x < 3) g_acc[threadIdx.x] = 0.0;
}

__device__ __forceinline__ double warp_reduce_d(double v) {
    #pragma unroll
    for (int o = 16; o > 0; o >>= 1)
        v += __shfl_down_sync(0xffffffffu, v, o);
    return v;
}

__global__ void __launch_bounds__(256) pmf_main_kernel(
    const int*    __restrict__ user,
    const int*    __restrict__ item,
    const float*  __restrict__ ratings,
    const float4* __restrict__ ue,   // user_embedding as float4 rows of 8
    const float4* __restrict__ ve)   // item_embedding as float4 rows of 8
{
    const int lane = threadIdx.x & 31;
    const int sub  = lane & 7;   // position within 8-lane group (dim chunk)
    const int grp  = lane >> 3;  // group 0..3 (interaction within quad)

    const int warp_id = (blockIdx.x * blockDim.x + threadIdx.x) >> 5;
    const int nwarps  = (gridDim.x * blockDim.x) >> 5;

    float bce = 0.0f;
    float uu  = 0.0f;
    float vv  = 0.0f;

    const int nchunks = BATCH / 32;   // 62500, each warp-chunk = 32 interactions
    for (int c = warp_id; c < nchunks; c += nwarps) {
        const int base = c * 32;
        // coalesced preload of 32 indices/ratings per warp
        const int   uidx = user[base + lane];
        const int   iidx = item[base + lane];
        const float rat  = ratings[base + lane];

        #pragma unroll
        for (int j = 0; j < 8; j++) {
            const int src = j * 4 + grp;  // which of the 32 preloaded interactions
            const int   ui = __shfl_sync(0xffffffffu, uidx, src);
            const int   ii = __shfl_sync(0xffffffffu, iidx, src);
            const float r  = __shfl_sync(0xffffffffu, rat,  src);

            // 8 lanes * float4 = 128B = one embedding row, one L2 line
            const float4 u = ue[ui * 8 + sub];
            const float4 v = ve[ii * 8 + sub];

            uu += u.x*u.x + u.y*u.y + u.z*u.z + u.w*u.w;
            vv += v.x*v.x + v.y*v.y + v.z*v.z + v.w*v.w;

            float p = u.x*v.x + u.y*v.y + u.z*v.z + u.w*v.w;
            // reduce within the 8-lane group
            p += __shfl_xor_sync(0xffffffffu, p, 4);
            p += __shfl_xor_sync(0xffffffffu, p, 2);
            p += __shfl_xor_sync(0xffffffffu, p, 1);

            if (sub == 0) {
                // stable BCE-with-logits: max(p,0) - p*r + log1p(exp(-|p|))
                bce += fmaxf(p, 0.0f) - p * r + log1pf(__expf(-fabsf(p)));
            }
        }
    }

    // Block reduction in double
    __shared__ double s_bce[8], s_uu[8], s_vv[8];
    const int wid_in_blk = threadIdx.x >> 5;

    double db = warp_reduce_d((double)bce);
    double du = warp_reduce_d((double)uu);
    double dv = warp_reduce_d((double)vv);
    if (lane == 0) {
        s_bce[wid_in_blk] = db;
        s_uu[wid_in_blk]  = du;
        s_vv[wid_in_blk]  = dv;
    }
    __syncthreads();
    if (wid_in_blk == 0) {
        double b2 = (lane < 8) ? s_bce[lane] : 0.0;
        double u2 = (lane < 8) ? s_uu[lane]  : 0.0;
        double v2 = (lane < 8) ? s_vv[lane]  : 0.0;
        b2 = warp_reduce_d(b2);
        u2 = warp_reduce_d(u2);
        v2 = warp_reduce_d(v2);
        if (lane == 0) {
            atomicAdd(&g_acc[0], b2);
            atomicAdd(&g_acc[1], u2);
            atomicAdd(&g_acc[2], v2);
        }
    }
}

__global__ void finalize_kernel(float* __restrict__ out) {
    double res = g_acc[0] + LAM * sqrt(g_acc[1]) + LAM * sqrt(g_acc[2]);
    out[0] = (float)res;
}

extern "C" void kernel_launch(void* const* d_in, const int* in_sizes, int n_in,
                              void* d_out, int out_size) {
    const int*    user = (const int*)d_in[0];
    const int*    item = (const int*)d_in[1];
    const float*  rat  = (const float*)d_in[2];
    const float4* ue   = (const float4*)d_in[3];
    const float4* ve   = (const float4*)d_in[4];
    float* out = (float*)d_out;

    zero_acc_kernel<<<1, 32>>>();
    const int threads = 256;
    const int blocks  = 148 * 8;  // grid-stride, ~9472 warps
    pmf_main_kernel<<<blocks, threads>>>(user, item, rat, ue, ve);
    finalize_kernel<<<1, 1>>>(out);
}